// round 10
// baseline (speedup 1.0000x reference)
#include <cuda_runtime.h>
#include <cuda_fp16.h>
#include <cstdint>

// Problem constants
#define BATCH 8
#define CI    64
#define CO    128
#define HH    128
#define WW    128
#define HW    (HH*WW)          // 16384

// Scratch: y = conv1x1(x), PIXEL-MAJOR, fp16: y[b][p][c]. 32 MiB.
__device__ __half g_y[BATCH * HW * CO];

// ---- packed f32x2 helpers (Blackwell FFMA2) --------------------------------
__device__ __forceinline__ unsigned long long pk2(float a, float b) {
    unsigned long long r;
    asm("mov.b64 %0, {%1, %2};" : "=l"(r) : "f"(a), "f"(b));
    return r;
}
__device__ __forceinline__ void fma2(unsigned long long& d,
                                     unsigned long long a,
                                     unsigned long long b) {
    asm("fma.rn.f32x2 %0, %1, %2, %0;" : "+l"(d) : "l"(a), "l"(b));
}
__device__ __forceinline__ void upk2(float& a, float& b, unsigned long long v) {
    asm("mov.b64 {%0, %1}, %2;" : "=f"(a), "=f"(b) : "l"(v));
}

// half2-pair (4 channels) -> float4
__device__ __forceinline__ float4 h2f4(uint2 u) {
    __half2 a = *reinterpret_cast<__half2*>(&u.x);
    __half2 b = *reinterpret_cast<__half2*>(&u.y);
    float2 fa = __half22float2(a);
    float2 fb = __half22float2(b);
    return make_float4(fa.x, fa.y, fb.x, fb.y);
}

// ---------------------------------------------------------------------------
// Kernel 1: 1x1 conv, FFMA2 GEMM (proven R8 core, unchanged).
// ---------------------------------------------------------------------------
__global__ void __launch_bounds__(256) conv1x1_kernel(const float* __restrict__ x,
                                                      const float* __restrict__ Wc,
                                                      const float* __restrict__ bc)
{
    extern __shared__ float sm[];
    float* Ws = sm;            // [i][o] 64*128 (Wc transposed)
    float* Xs = sm + 64 * 128; // [i][p] 64*128

    const int b   = blockIdx.y;
    const int p0  = blockIdx.x * 128;
    const int tid = threadIdx.x;

    for (int idx = tid; idx < 64 * 128; idx += 256) {
        int i = idx >> 7;
        int o = idx & 127;
        Ws[idx] = Wc[o * CI + i];
    }
    {
        const float4* xb4 = reinterpret_cast<const float4*>(x + (size_t)b * CI * HW);
        float4* Xs4 = reinterpret_cast<float4*>(Xs);
        for (int idx = tid; idx < 2048; idx += 256) {
            int i  = idx >> 5;
            int p4 = idx & 31;
            Xs4[idx] = xb4[i * (HW / 4) + (p0 >> 2) + p4];
        }
    }
    __syncthreads();

    const int tx = tid & 15;   // channel group
    const int ty = tid >> 4;   // pixel group

    unsigned long long acc2[4][8];
#pragma unroll
    for (int q = 0; q < 4; ++q)
#pragma unroll
        for (int k = 0; k < 8; ++k) acc2[q][k] = 0ull;

    const float4* Ws4 = reinterpret_cast<const float4*>(Ws);

#pragma unroll 4
    for (int i = 0; i < 64; ++i) {
        float4 w0 = Ws4[i * 32 + tx];
        float4 w1 = Ws4[i * 32 + 16 + tx];

        const float* xrow = Xs + i * 128;
        ulonglong2 xa = *reinterpret_cast<const ulonglong2*>(xrow + ty * 8);
        ulonglong2 xb = *reinterpret_cast<const ulonglong2*>(xrow + ty * 8 + 4);
        unsigned long long xp[4] = {xa.x, xa.y, xb.x, xb.y};

        unsigned long long wd[8];
        wd[0] = pk2(w0.x, w0.x); wd[1] = pk2(w0.y, w0.y);
        wd[2] = pk2(w0.z, w0.z); wd[3] = pk2(w0.w, w0.w);
        wd[4] = pk2(w1.x, w1.x); wd[5] = pk2(w1.y, w1.y);
        wd[6] = pk2(w1.z, w1.z); wd[7] = pk2(w1.w, w1.w);

#pragma unroll
        for (int q = 0; q < 4; ++q)
#pragma unroll
            for (int k = 0; k < 8; ++k)
                fma2(acc2[q][k], xp[q], wd[k]);
    }

    float bv[8];
#pragma unroll
    for (int k = 0; k < 4; ++k) {
        bv[k]     = bc[tx * 4 + k];
        bv[k + 4] = bc[64 + tx * 4 + k];
    }

    __half* yb = g_y + ((size_t)b * HW + p0) * CO;
#pragma unroll
    for (int q = 0; q < 4; ++q) {
#pragma unroll
        for (int half = 0; half < 2; ++half) {
            float e[8];
#pragma unroll
            for (int k = 0; k < 8; ++k) {
                float lo, hi;
                upk2(lo, hi, acc2[q][k]);
                e[k] = (half == 0 ? lo : hi) + bv[k];
            }
            __half* dst = yb + (size_t)(ty * 8 + q * 2 + half) * CO;
            __half2 h0 = __floats2half2_rn(e[0], e[1]);
            __half2 h1 = __floats2half2_rn(e[2], e[3]);
            __half2 h2 = __floats2half2_rn(e[4], e[5]);
            __half2 h3 = __floats2half2_rn(e[6], e[7]);
            *reinterpret_cast<uint2*>(dst + tx * 4) =
                make_uint2(*reinterpret_cast<uint32_t*>(&h0),
                           *reinterpret_cast<uint32_t*>(&h1));
            *reinterpret_cast<uint2*>(dst + 64 + tx * 4) =
                make_uint2(*reinterpret_cast<uint32_t*>(&h2),
                           *reinterpret_cast<uint32_t*>(&h3));
        }
    }
}

// ---------------------------------------------------------------------------
// Kernel 2: 3x3 local attention, warp per 1x2 strip, split-butterfly reduce,
// CTA-cooperative smem halo staging: 3x18 vecs loaded once per CTA (54 LDG
// vectors vs 96), warps read their 3x4 windows via conflict-free LDS.64.
// ---------------------------------------------------------------------------
#define NVEC 54          // 3 rows x 18 cols

__global__ void __launch_bounds__(256) attn3x3_kernel(float* __restrict__ out)
{
    __shared__ uint2  sv[NVEC * 32];   // [vec][lane4] fp16 channel data (13.5KB)
    __shared__ float  so[16 * CO];     // [pix][c] output stage (8KB)

    const int tid  = threadIdx.x;
    const int wid  = tid >> 5;
    const int lane = tid & 31;

    const int g16 = blockIdx.x * 16;
    const int b   = g16 >> 14;
    const int p   = g16 & (HW - 1);
    const int h   = p >> 7;
    const int wc  = p & (WW - 1);

    // ---- Stage halo: rows h-1..h+1, cols wc-1..wc+16, zero-padded ----
    {
        const __half* yb = g_y + ((size_t)b * HW) * CO;
#pragma unroll
        for (int it = 0; it < 7; ++it) {
            int idx = tid + it * 256;
            if (idx < NVEC * 32) {
                int vec   = idx >> 5;
                int lane4 = idx & 31;
                int r  = vec / 18;
                int cc = vec - r * 18;
                int gh = h - 1 + r;
                int gw = wc - 1 + cc;
                uint2 u = make_uint2(0u, 0u);
                if ((unsigned)gh < HH && (unsigned)gw < WW) {
                    u = *reinterpret_cast<const uint2*>(
                        yb + (size_t)(gh * WW + gw) * CO + lane4 * 4);
                }
                sv[idx] = u;
            }
        }
    }
    __syncthreads();

    // ---- Load this warp's 3x4 window from smem, convert once to fp32 ----
    float4 v[3][4];
#pragma unroll
    for (int r = 0; r < 3; ++r)
#pragma unroll
        for (int c = 0; c < 4; ++c)
            v[r][c] = h2f4(sv[(r * 18 + wid * 2 + c) * 32 + lane]);

    const float scale = 0.08838834764831845f; // 1/sqrt(128)
    const bool loHalf = lane < 16;

    // Per-lane partial scores for both pixels
    float sA[9], sB[9];
    {
        const float4 midA = v[1][1];
        const float4 midB = v[1][2];
#pragma unroll
        for (int n = 0; n < 9; ++n) {
            const float4 qa = v[n / 3][n % 3];
            const float4 qb = v[n / 3][n % 3 + 1];
            sA[n] = qa.x * midA.x + qa.y * midA.y + qa.z * midA.z + qa.w * midA.w;
            sB[n] = qb.x * midB.x + qb.y * midB.y + qb.z * midB.z + qb.w * midB.w;
        }
    }

    // Stage 16: fold both pixels, pack A into lanes 0-15, B into lanes 16-31
    float s[9];
#pragma unroll
    for (int n = 0; n < 9; ++n) {
        float tA = sA[n] + __shfl_xor_sync(0xffffffffu, sA[n], 16);
        float tB = sB[n] + __shfl_xor_sync(0xffffffffu, sB[n], 16);
        s[n] = loHalf ? tA : tB;
    }
#pragma unroll
    for (int off = 8; off > 0; off >>= 1) {
#pragma unroll
        for (int n = 0; n < 9; ++n)
            s[n] += __shfl_xor_sync(0xffffffffu, s[n], off);
    }

    // Softmax (no max-subtraction: s*scale bounded ~20, exp safe in fp32)
    float a[9], den = 0.f;
#pragma unroll
    for (int n = 0; n < 9; ++n) {
        a[n] = __expf(s[n] * scale);
        den += a[n];
    }
    float inv = 1.0f / den;

    // Normalize and exchange weights across halves
    float wA[9], wB[9];
#pragma unroll
    for (int n = 0; n < 9; ++n) {
        float an = a[n] * inv;
        float other = __shfl_xor_sync(0xffffffffu, an, 16);
        wA[n] = loHalf ? an : other;
        wB[n] = loHalf ? other : an;
    }

    // Weighted sums (both pixels), write to smem stage
    float4 oA = make_float4(0.f, 0.f, 0.f, 0.f);
    float4 oB = make_float4(0.f, 0.f, 0.f, 0.f);
#pragma unroll
    for (int n = 0; n < 9; ++n) {
        const float4 qa = v[n / 3][n % 3];
        const float4 qb = v[n / 3][n % 3 + 1];
        oA.x = fmaf(wA[n], qa.x, oA.x);
        oA.y = fmaf(wA[n], qa.y, oA.y);
        oA.z = fmaf(wA[n], qa.z, oA.z);
        oA.w = fmaf(wA[n], qa.w, oA.w);
        oB.x = fmaf(wB[n], qb.x, oB.x);
        oB.y = fmaf(wB[n], qb.y, oB.y);
        oB.z = fmaf(wB[n], qb.z, oB.z);
        oB.w = fmaf(wB[n], qb.w, oB.w);
    }

    *reinterpret_cast<float4*>(&so[(wid * 2 + 0) * CO + lane * 4]) = oA;
    *reinterpret_cast<float4*>(&so[(wid * 2 + 1) * CO + lane * 4]) = oB;
    __syncthreads();

    // Transposed, channel-major store
    {
        const int c  = tid >> 1;
        const int qb = (tid & 1) * 2;
        float* dst = out + ((size_t)b * CO + c) * HW + h * WW + wc;
#pragma unroll
        for (int j = 0; j < 2; ++j) {
            int q = qb + j;
            float4 r;
            r.x = so[(q * 4 + 0) * CO + c];
            r.y = so[(q * 4 + 1) * CO + c];
            r.z = so[(q * 4 + 2) * CO + c];
            r.w = so[(q * 4 + 3) * CO + c];
            *reinterpret_cast<float4*>(dst + q * 4) = r;
        }
    }
}

// ---------------------------------------------------------------------------
extern "C" void kernel_launch(void* const* d_in, const int* in_sizes, int n_in,
                              void* d_out, int out_size)
{
    const float* x  = nullptr;
    const float* Wc = nullptr;
    const float* bc = nullptr;
    for (int i = 0; i < n_in; ++i) {
        if (in_sizes[i] == BATCH * CI * HW) x  = (const float*)d_in[i];
        else if (in_sizes[i] == CO * CI)    Wc = (const float*)d_in[i];
        else if (in_sizes[i] == CO)         bc = (const float*)d_in[i];
    }
    float* out = (float*)d_out;

    static const int conv_smem = 64 * 128 * 2 * sizeof(float);   // 65536

    cudaFuncSetAttribute(conv1x1_kernel,
                         cudaFuncAttributeMaxDynamicSharedMemorySize, conv_smem);

    conv1x1_kernel<<<dim3(HW / 128, BATCH), 256, conv_smem>>>(x, Wc, bc);
    attn3x3_kernel<<<BATCH * HW / 16, 256>>>(out);
}

// round 11
// speedup vs baseline: 1.1031x; 1.1031x over previous
#include <cuda_runtime.h>
#include <cuda_fp16.h>
#include <cstdint>

// Problem constants
#define BATCH 8
#define CI    64
#define CO    128
#define HH    128
#define WW    128
#define HW    (HH*WW)          // 16384

// Scratch: y = conv1x1(x), PIXEL-MAJOR, fp16: y[b][p][c]. 32 MiB.
__device__ __half g_y[BATCH * HW * CO];

// ---- packed f32x2 helpers (Blackwell FFMA2) --------------------------------
__device__ __forceinline__ unsigned long long pk2(float a, float b) {
    unsigned long long r;
    asm("mov.b64 %0, {%1, %2};" : "=l"(r) : "f"(a), "f"(b));
    return r;
}
__device__ __forceinline__ void fma2(unsigned long long& d,
                                     unsigned long long a,
                                     unsigned long long b) {
    asm("fma.rn.f32x2 %0, %1, %2, %0;" : "+l"(d) : "l"(a), "l"(b));
}
__device__ __forceinline__ void upk2(float& a, float& b, unsigned long long v) {
    asm("mov.b64 {%0, %1}, %2;" : "=f"(a), "=f"(b) : "l"(v));
}

// half2-pair (4 channels) -> float4
__device__ __forceinline__ float4 h2f4(uint2 u) {
    __half2 a = *reinterpret_cast<__half2*>(&u.x);
    __half2 b = *reinterpret_cast<__half2*>(&u.y);
    float2 fa = __half22float2(a);
    float2 fb = __half22float2(b);
    return make_float4(fa.x, fa.y, fb.x, fb.y);
}
__device__ __forceinline__ float dot4(float4 a, float4 b) {
    float r = a.x * b.x;
    r = fmaf(a.y, b.y, r);
    r = fmaf(a.z, b.z, r);
    r = fmaf(a.w, b.w, r);
    return r;
}

// ---------------------------------------------------------------------------
// Kernel 1: 1x1 conv, FFMA2 GEMM (proven R8 core, unchanged).
// ---------------------------------------------------------------------------
__global__ void __launch_bounds__(256) conv1x1_kernel(const float* __restrict__ x,
                                                      const float* __restrict__ Wc,
                                                      const float* __restrict__ bc)
{
    extern __shared__ float sm[];
    float* Ws = sm;            // [i][o] 64*128 (Wc transposed)
    float* Xs = sm + 64 * 128; // [i][p] 64*128

    const int b   = blockIdx.y;
    const int p0  = blockIdx.x * 128;
    const int tid = threadIdx.x;

    for (int idx = tid; idx < 64 * 128; idx += 256) {
        int i = idx >> 7;
        int o = idx & 127;
        Ws[idx] = Wc[o * CI + i];
    }
    {
        const float4* xb4 = reinterpret_cast<const float4*>(x + (size_t)b * CI * HW);
        float4* Xs4 = reinterpret_cast<float4*>(Xs);
        for (int idx = tid; idx < 2048; idx += 256) {
            int i  = idx >> 5;
            int p4 = idx & 31;
            Xs4[idx] = xb4[i * (HW / 4) + (p0 >> 2) + p4];
        }
    }
    __syncthreads();

    const int tx = tid & 15;   // channel group
    const int ty = tid >> 4;   // pixel group

    unsigned long long acc2[4][8];
#pragma unroll
    for (int q = 0; q < 4; ++q)
#pragma unroll
        for (int k = 0; k < 8; ++k) acc2[q][k] = 0ull;

    const float4* Ws4 = reinterpret_cast<const float4*>(Ws);

#pragma unroll 4
    for (int i = 0; i < 64; ++i) {
        float4 w0 = Ws4[i * 32 + tx];
        float4 w1 = Ws4[i * 32 + 16 + tx];

        const float* xrow = Xs + i * 128;
        ulonglong2 xa = *reinterpret_cast<const ulonglong2*>(xrow + ty * 8);
        ulonglong2 xb = *reinterpret_cast<const ulonglong2*>(xrow + ty * 8 + 4);
        unsigned long long xp[4] = {xa.x, xa.y, xb.x, xb.y};

        unsigned long long wd[8];
        wd[0] = pk2(w0.x, w0.x); wd[1] = pk2(w0.y, w0.y);
        wd[2] = pk2(w0.z, w0.z); wd[3] = pk2(w0.w, w0.w);
        wd[4] = pk2(w1.x, w1.x); wd[5] = pk2(w1.y, w1.y);
        wd[6] = pk2(w1.z, w1.z); wd[7] = pk2(w1.w, w1.w);

#pragma unroll
        for (int q = 0; q < 4; ++q)
#pragma unroll
            for (int k = 0; k < 8; ++k)
                fma2(acc2[q][k], xp[q], wd[k]);
    }

    float bv[8];
#pragma unroll
    for (int k = 0; k < 4; ++k) {
        bv[k]     = bc[tx * 4 + k];
        bv[k + 4] = bc[64 + tx * 4 + k];
    }

    __half* yb = g_y + ((size_t)b * HW + p0) * CO;
#pragma unroll
    for (int q = 0; q < 4; ++q) {
#pragma unroll
        for (int half = 0; half < 2; ++half) {
            float e[8];
#pragma unroll
            for (int k = 0; k < 8; ++k) {
                float lo, hi;
                upk2(lo, hi, acc2[q][k]);
                e[k] = (half == 0 ? lo : hi) + bv[k];
            }
            __half* dst = yb + (size_t)(ty * 8 + q * 2 + half) * CO;
            __half2 h0 = __floats2half2_rn(e[0], e[1]);
            __half2 h1 = __floats2half2_rn(e[2], e[3]);
            __half2 h2 = __floats2half2_rn(e[4], e[5]);
            __half2 h3 = __floats2half2_rn(e[6], e[7]);
            *reinterpret_cast<uint2*>(dst + tx * 4) =
                make_uint2(*reinterpret_cast<uint32_t*>(&h0),
                           *reinterpret_cast<uint32_t*>(&h1));
            *reinterpret_cast<uint2*>(dst + 64 + tx * 4) =
                make_uint2(*reinterpret_cast<uint32_t*>(&h2),
                           *reinterpret_cast<uint32_t*>(&h3));
        }
    }
}

// ---------------------------------------------------------------------------
// Kernel 2: 3x3 local attention, warp per 2x2 pixel BLOCK.
// Warp loads its 4x4 fp16 neighborhood once (16 LDG.64 = 4/px), quarter-split
// butterfly reduces all 4 pixels' scores at once (lanes 0-7=A, 8-15=B,
// 16-23=C, 24-31=D), softmax per quarter (9 exp/warp for 4 px), weights
// broadcast via smem, weighted sums from registers.
// CTA = 8 warps = 16(w) x 2(h) pixel tile.
// ---------------------------------------------------------------------------
__global__ void __launch_bounds__(256, 2) attn3x3_kernel(float* __restrict__ out)
{
    __shared__ float so[32 * CO];        // [px(row*16+col)][c]  16KB
    __shared__ float wsm[8][4][12];      // [warp][pixel][9 weights]

    const int tid  = threadIdx.x;
    const int wid  = tid >> 5;
    const int lane = tid & 31;

    const int b  = blockIdx.z;
    const int r0 = blockIdx.y * 2;          // tile rows r0, r0+1
    const int wc = blockIdx.x * 16;         // tile cols wc..wc+15
    const int c0 = wc + wid * 2;            // this warp's 2 cols

    const __half* ybase = g_y + ((size_t)b * HW) * CO + lane * 4;

    // Load 4x4 fp16 neighborhood (rows r0-1..r0+2, cols c0-1..c0+2)
    float4 v[4][4];
#pragma unroll
    for (int r = 0; r < 4; ++r) {
        int gh = r0 - 1 + r;
#pragma unroll
        for (int c = 0; c < 4; ++c) {
            int gw = c0 - 1 + c;
            if ((unsigned)gh < HH && (unsigned)gw < WW) {
                v[r][c] = h2f4(*reinterpret_cast<const uint2*>(
                    ybase + (size_t)(gh * WW + gw) * CO));
            } else {
                v[r][c] = make_float4(0.f, 0.f, 0.f, 0.f);
            }
        }
    }

    const float scale = 0.08838834764831845f; // 1/sqrt(128)
    const bool loHalf = lane < 16;
    const int  q8     = (lane >> 3) & 3;      // quarter: 0=A 1=B 2=C 3=D

    // Scores: fold per n inside the loop (keeps registers low).
    // Pixel A=(0,0) B=(0,1) C=(1,0) D=(1,1); center v[i+1][j+1].
    float s[9];
    {
        const float4 mA = v[1][1], mB = v[1][2], mC = v[2][1], mD = v[2][2];
#pragma unroll
        for (int n = 0; n < 9; ++n) {
            const int di = n / 3, dj = n % 3;
            float sA = dot4(v[di][dj],     mA);
            float sB = dot4(v[di][dj + 1], mB);
            float sC = dot4(v[di + 1][dj],     mC);
            float sD = dot4(v[di + 1][dj + 1], mD);
            // stage 16: fold each, pack into two arrays
            float fA = sA + __shfl_xor_sync(0xffffffffu, sA, 16);
            float fB = sB + __shfl_xor_sync(0xffffffffu, sB, 16);
            float fC = sC + __shfl_xor_sync(0xffffffffu, sC, 16);
            float fD = sD + __shfl_xor_sync(0xffffffffu, sD, 16);
            float sLo = loHalf ? fA : fC;
            float sHi = loHalf ? fB : fD;
            // stage 8: fold both, pack into quarters
            float gLo = sLo + __shfl_xor_sync(0xffffffffu, sLo, 8);
            float gHi = sHi + __shfl_xor_sync(0xffffffffu, sHi, 8);
            s[n] = (lane & 8) ? gHi : gLo;
        }
    }
    // stages 4,2,1 within each 8-lane quarter
#pragma unroll
    for (int off = 4; off > 0; off >>= 1) {
#pragma unroll
        for (int n = 0; n < 9; ++n)
            s[n] += __shfl_xor_sync(0xffffffffu, s[n], off);
    }

    // Softmax for this lane's quarter-pixel (no max-sub: s*scale bounded)
    float a[9], den = 0.f;
#pragma unroll
    for (int n = 0; n < 9; ++n) {
        a[n] = __expf(s[n] * scale);
        den += a[n];
    }
    float inv = 1.0f / den;

    // Broadcast normalized weights via smem (one writer lane per quarter)
    if ((lane & 7) == 0) {
#pragma unroll
        for (int n = 0; n < 9; ++n)
            wsm[wid][q8][n] = a[n] * inv;
    }
    __syncwarp(0xffffffffu);

    // Weighted sums for all 4 pixels (weights read as smem broadcasts)
    float4 oA = make_float4(0.f, 0.f, 0.f, 0.f);
    float4 oB = oA, oC = oA, oD = oA;
#pragma unroll
    for (int n = 0; n < 9; ++n) {
        const int di = n / 3, dj = n % 3;
        const float wA = wsm[wid][0][n];
        const float wB = wsm[wid][1][n];
        const float wC = wsm[wid][2][n];
        const float wD = wsm[wid][3][n];
        const float4 qa = v[di][dj];
        const float4 qb = v[di][dj + 1];
        const float4 qc = v[di + 1][dj];
        const float4 qd = v[di + 1][dj + 1];
        oA.x = fmaf(wA, qa.x, oA.x); oA.y = fmaf(wA, qa.y, oA.y);
        oA.z = fmaf(wA, qa.z, oA.z); oA.w = fmaf(wA, qa.w, oA.w);
        oB.x = fmaf(wB, qb.x, oB.x); oB.y = fmaf(wB, qb.y, oB.y);
        oB.z = fmaf(wB, qb.z, oB.z); oB.w = fmaf(wB, qb.w, oB.w);
        oC.x = fmaf(wC, qc.x, oC.x); oC.y = fmaf(wC, qc.y, oC.y);
        oC.z = fmaf(wC, qc.z, oC.z); oC.w = fmaf(wC, qc.w, oC.w);
        oD.x = fmaf(wD, qd.x, oD.x); oD.y = fmaf(wD, qd.y, oD.y);
        oD.z = fmaf(wD, qd.z, oD.z); oD.w = fmaf(wD, qd.w, oD.w);
    }

    // Stage [px][c]: px = row*16 + col
    {
        const int colA = wid * 2;
        *reinterpret_cast<float4*>(&so[(0 * 16 + colA)     * CO + lane * 4]) = oA;
        *reinterpret_cast<float4*>(&so[(0 * 16 + colA + 1) * CO + lane * 4]) = oB;
        *reinterpret_cast<float4*>(&so[(1 * 16 + colA)     * CO + lane * 4]) = oC;
        *reinterpret_cast<float4*>(&so[(1 * 16 + colA + 1) * CO + lane * 4]) = oD;
    }
    __syncthreads();

    // Transposed, channel-major store: thread t -> channel c = t>>1,
    // part = t&1 -> cols part*8..part*8+7, both rows.
    {
        const int c    = tid >> 1;
        const int part = tid & 1;
        float* dst = out + ((size_t)b * CO + c) * HW + r0 * WW + wc + part * 8;
#pragma unroll
        for (int row = 0; row < 2; ++row) {
#pragma unroll
            for (int q = 0; q < 2; ++q) {
                int col = part * 8 + q * 4;
                float4 r;
                r.x = so[(row * 16 + col + 0) * CO + c];
                r.y = so[(row * 16 + col + 1) * CO + c];
                r.z = so[(row * 16 + col + 2) * CO + c];
                r.w = so[(row * 16 + col + 3) * CO + c];
                *reinterpret_cast<float4*>(dst + row * WW + q * 4) = r;
            }
        }
    }
}

// ---------------------------------------------------------------------------
extern "C" void kernel_launch(void* const* d_in, const int* in_sizes, int n_in,
                              void* d_out, int out_size)
{
    const float* x  = nullptr;
    const float* Wc = nullptr;
    const float* bc = nullptr;
    for (int i = 0; i < n_in; ++i) {
        if (in_sizes[i] == BATCH * CI * HW) x  = (const float*)d_in[i];
        else if (in_sizes[i] == CO * CI)    Wc = (const float*)d_in[i];
        else if (in_sizes[i] == CO)         bc = (const float*)d_in[i];
    }
    float* out = (float*)d_out;

    static const int conv_smem = 64 * 128 * 2 * sizeof(float);   // 65536

    cudaFuncSetAttribute(conv1x1_kernel,
                         cudaFuncAttributeMaxDynamicSharedMemorySize, conv_smem);

    conv1x1_kernel<<<dim3(HW / 128, BATCH), 256, conv_smem>>>(x, Wc, bc);
    attn3x3_kernel<<<dim3(WW / 16, HH / 2, BATCH), 256>>>(out);
}